// round 5
// baseline (speedup 1.0000x reference)
#include <cuda_runtime.h>

// Shapes (fixed by the problem):
//   x  : (32, 3, 640, 640) fp32
//   W1 : (192, 64), b1 : (64), W2 : (64, 15)
#define B    32
#define C    3
#define H    640
#define W    640
#define HW   (H * W)        // 409600 floats per channel
#define HW4  (HW / 4)       // 102400 float4 per channel
#define POOL 8
#define HID  64
#define NP   15             // 9 (M) + 3 (bias) + 3 (gamma)
#define TGRID (HW4 / 512)   // transform grid.x = 200
#define CHUNK 16            // samples per pipeline chunk (16*4.9MB = 78MB < L2)

// Scratch (allocation-free rule: __device__ globals)
__device__ float g_pooled[B * C * POOL * POOL];   // (b, c*64 + pr*8 + pc)
__device__ float g_params[B * NP];                // per-sample sigmoid outputs
__device__ int   g_count[B];                      // zero-init; reset by last block

// ---------------------------------------------------------------------------
// Kernel 1: adaptive avg pool 8x8 over a CHUNK of samples, with the per-sample
// MLP fused via the last-block pattern.
// Grid: CHUNK*C*POOL = 384 blocks, one per (b_local, c, pool-row). 320 threads.
// Thread owns float4-column f = tid%160, row-parity r0 = tid/160; streams 40
// fixed-stride rows so ptxas front-batches the loads.
// The 24th (last) finishing block of each sample runs the tiny MLP:
//   hid = clip(feat @ W1 + b1, 0, 6);  params = sigmoid(hid @ W2)
// Deterministic: MLP inputs are the completed pooled feats regardless of
// which block computes them; counter is reset for the next graph replay.
// ---------------------------------------------------------------------------
__global__ __launch_bounds__(320) void pool_mlp_kernel(const float* __restrict__ x,
                                                       const float* __restrict__ W1,
                                                       const float* __restrict__ b1,
                                                       const float* __restrict__ W2,
                                                       int b_base) {
    int id = blockIdx.x;              // b_local*24 + c*8 + pr
    int pr = id & 7;
    int bcl = id >> 3;                // b_local*3 + c
    int bc  = b_base * 3 + bcl;       // global (b*3 + c)
    int b   = b_base + bcl / 3;       // global sample

    int tid = threadIdx.x;
    int f   = tid % 160;              // float4 column within the row (640/4)
    int r0  = tid / 160;              // 0 or 1

    const float4* base = reinterpret_cast<const float4*>(x)
                       + (size_t)bc * HW4 + (size_t)pr * (80 * 160) + f
                       + (size_t)r0 * 160;

    float acc = 0.0f;
    #pragma unroll
    for (int r = 0; r < 40; r++) {                 // rows r0, r0+2, ..., 78/79
        float4 v = base[(size_t)r * 320];          // stride = 2 rows
        acc += (v.x + v.y) + (v.z + v.w);
    }

    __shared__ float s[320];
    s[tid] = acc;
    __syncthreads();

    if (tid < 8) {                                 // tid == pool column pc
        float t = 0.0f;
        #pragma unroll
        for (int k = 0; k < 20; k++)
            t += s[tid * 20 + k] + s[160 + tid * 20 + k];
        g_pooled[bc * 64 + pr * 8 + tid] = t * (1.0f / 6400.0f);
    }
    __syncthreads();                               // pooled writes done block-wide

    // Last-block election for this sample (24 blocks per sample).
    __shared__ int s_last;
    if (tid == 0) {
        __threadfence();                           // publish g_pooled before count
        s_last = (atomicAdd(&g_count[b], 1) == C * POOL - 1);
    }
    __syncthreads();
    if (!s_last) return;

    // ---- fused MLP for sample b (first 64 threads) ----
    __shared__ float feat[C * POOL * POOL];        // 192
    __shared__ float hid[HID];
    if (tid < 192)
        feat[tid] = __ldcg(&g_pooled[b * 192 + tid]);   // L1-bypass: other blocks wrote
    __syncthreads();

    if (tid < HID) {
        float sum = b1[tid];
        #pragma unroll 8
        for (int j = 0; j < 192; j++)
            sum = fmaf(feat[j], W1[j * HID + tid], sum);
        hid[tid] = fminf(fmaxf(sum, 0.0f), 6.0f);
    }
    __syncthreads();

    if (tid < NP) {
        float s2 = 0.0f;
        #pragma unroll 8
        for (int j = 0; j < HID; j++)
            s2 = fmaf(hid[j], W2[j * NP + tid], s2);
        g_params[b * NP + tid] = 1.0f / (1.0f + __expf(-s2));
    }
    if (tid == 0) g_count[b] = 0;                  // reset for next graph replay
}

// ---------------------------------------------------------------------------
// Kernel 2: per-pixel 3x3 color transform + pow(gamma) + normalize over the
// SAME chunk pool just loaded: the 78 MB of x is L2-resident -> re-read hits
// L2 instead of DRAM. Output stores streaming (__stcs, evict-first) so the
// write stream doesn't displace the chunk.
// Grid: (TGRID, CHUNK), 256 threads; 2 float4 per plane per thread.
// ---------------------------------------------------------------------------
__global__ __launch_bounds__(256) void transform_kernel(const float* __restrict__ x,
                                                        float* __restrict__ out,
                                                        int b_base) {
    int b = b_base + blockIdx.y;
    __shared__ float sp[NP];
    if (threadIdx.x < NP) sp[threadIdx.x] = g_params[b * NP + threadIdx.x];
    __syncthreads();

    int idx = blockIdx.x * 512 + threadIdx.x;       // first float4; second at +256
    const float4* xb = reinterpret_cast<const float4*>(x)   + (size_t)b * 3 * HW4 + idx;
    float4*       ob = reinterpret_cast<float4*>(out)       + (size_t)b * 3 * HW4 + idx;

    // Batch all 6 loads up front.
    float4 a0 = xb[0];
    float4 a1 = xb[HW4];
    float4 a2 = xb[2 * HW4];
    float4 c0 = xb[256];
    float4 c1 = xb[HW4 + 256];
    float4 c2 = xb[2 * HW4 + 256];

    const float mean_[3] = {0.485f, 0.456f, 0.406f};
    const float istd_[3] = {1.0f / 0.229f, 1.0f / 0.224f, 1.0f / 0.225f};

    #pragma unroll
    for (int i = 0; i < 3; i++) {
        float m0 = sp[i * 3 + 0], m1 = sp[i * 3 + 1], m2 = sp[i * 3 + 2];
        float bi = sp[9 + i];
        float g  = sp[12 + i];
        float is = istd_[i];
        float mo = mean_[i] * is;

        float4 r, q;
        r.x = __powf(fmaf(m0, a0.x, fmaf(m1, a1.x, fmaf(m2, a2.x, bi))), g) * is - mo;
        r.y = __powf(fmaf(m0, a0.y, fmaf(m1, a1.y, fmaf(m2, a2.y, bi))), g) * is - mo;
        r.z = __powf(fmaf(m0, a0.z, fmaf(m1, a1.z, fmaf(m2, a2.z, bi))), g) * is - mo;
        r.w = __powf(fmaf(m0, a0.w, fmaf(m1, a1.w, fmaf(m2, a2.w, bi))), g) * is - mo;
        q.x = __powf(fmaf(m0, c0.x, fmaf(m1, c1.x, fmaf(m2, c2.x, bi))), g) * is - mo;
        q.y = __powf(fmaf(m0, c0.y, fmaf(m1, c1.y, fmaf(m2, c2.y, bi))), g) * is - mo;
        q.z = __powf(fmaf(m0, c0.z, fmaf(m1, c1.z, fmaf(m2, c2.z, bi))), g) * is - mo;
        q.w = __powf(fmaf(m0, c0.w, fmaf(m1, c1.w, fmaf(m2, c2.w, bi))), g) * is - mo;
        __stcs(&ob[(size_t)i * HW4], r);
        __stcs(&ob[(size_t)i * HW4 + 256], q);
    }
}

// ---------------------------------------------------------------------------
extern "C" void kernel_launch(void* const* d_in, const int* in_sizes, int n_in,
                              void* d_out, int out_size) {
    const float* x  = (const float*)d_in[0];
    const float* W1 = (const float*)d_in[1];
    const float* b1 = (const float*)d_in[2];
    const float* W2 = (const float*)d_in[3];
    float* out = (float*)d_out;

    for (int g = 0; g < B / CHUNK; g++) {
        pool_mlp_kernel<<<CHUNK * C * POOL, 320>>>(x, W1, b1, W2, g * CHUNK);
        transform_kernel<<<dim3(TGRID, CHUNK), 256>>>(x, out, g * CHUNK);
    }
}